// round 1
// baseline (speedup 1.0000x reference)
#include <cuda_runtime.h>
#include <cstdint>

#define Bn 64
#define Sn 128
#define Dn 512
#define Tn 64
#define N3 1536      // 3*D
#define GK 515       // D + 3
#define GKP 528      // padded to multiple of 16

// ---------------- scratch (device globals; no allocation) ----------------
__device__ float g_Uk[Bn * Sn * Dn];        // [B,S,D] keys projection
__device__ float g_h[Bn * Dn];              // hidden state
__device__ float g_qpart[4][Bn * Dn];       // split-K partials of q
__device__ float g_ghpart[4][Bn * N3];      // split-K partials of gh
__device__ float g_gipart[4][Bn * N3];      // split-K partials of gi
__device__ float g_gin[Bn * GKP];           // [ctx | x | zero-pad]
__device__ float g_Wpad[N3 * GKP];          // W_ih zero-padded to K=528

__device__ __forceinline__ float tanh_fast(float x) {
    float y; asm("tanh.approx.f32 %0, %1;" : "=f"(y) : "f"(x)); return y;
}

struct SmemGemm { float As[16][68]; float Bs[16][68]; };

// C[64 x 64] tile of  C = A(MxK) * B  (+bias), BK=16, 256 threads, 4x4 microtile.
// NT=false: B is row-major [K,N] (use B[k,n]);  NT=true: B is row-major [N,K] (use B[n,k]).
template <bool NT>
__device__ __forceinline__ void gemm64(const float* __restrict__ A, int lda,
                                       const float* __restrict__ B, int ldb,
                                       float* __restrict__ C, int ldc,
                                       const float* __restrict__ bias,
                                       int m0, int n0, int k0, int kiters,
                                       SmemGemm& s)
{
    const int tid = threadIdx.x;
    const int tx = tid & 15, ty = tid >> 4;
    const int am = tid >> 2, ak = (tid & 3) << 2;   // A: row am, 4 consecutive k
    float acc[4][4] = {};

    for (int it = 0; it < kiters; ++it) {
        const int k = k0 + it * 16;
        float4 a4 = *(const float4*)&A[(size_t)(m0 + am) * lda + k + ak];
        float4 b4;
        if (NT) {
            // B row-major [N,K]: thread loads 4 consecutive k of row n0+am
            b4 = *(const float4*)&B[(size_t)(n0 + am) * ldb + k + ak];
        } else {
            // B row-major [K,N]: thread loads 4 consecutive n of row k+bk
            const int bk = tid >> 4, bn = (tid & 15) << 2;
            b4 = *(const float4*)&B[(size_t)(k + bk) * ldb + n0 + bn];
        }
        __syncthreads();
        s.As[ak + 0][am] = a4.x; s.As[ak + 1][am] = a4.y;
        s.As[ak + 2][am] = a4.z; s.As[ak + 3][am] = a4.w;
        if (NT) {
            s.Bs[ak + 0][am] = b4.x; s.Bs[ak + 1][am] = b4.y;
            s.Bs[ak + 2][am] = b4.z; s.Bs[ak + 3][am] = b4.w;
        } else {
            const int bk = tid >> 4, bn = (tid & 15) << 2;
            *(float4*)&s.Bs[bk][bn] = b4;
        }
        __syncthreads();
        #pragma unroll
        for (int kk = 0; kk < 16; ++kk) {
            float4 av = *(const float4*)&s.As[kk][ty << 2];
            float4 bv = *(const float4*)&s.Bs[kk][tx << 2];
            float a[4] = {av.x, av.y, av.z, av.w};
            float b[4] = {bv.x, bv.y, bv.z, bv.w};
            #pragma unroll
            for (int u = 0; u < 4; ++u)
                #pragma unroll
                for (int v = 0; v < 4; ++v)
                    acc[u][v] += a[u] * b[v];
        }
    }

    float4 bi = make_float4(0.f, 0.f, 0.f, 0.f);
    if (bias) bi = *(const float4*)&bias[n0 + (tx << 2)];
    #pragma unroll
    for (int u = 0; u < 4; ++u) {
        float4 o;
        o.x = acc[u][0] + bi.x; o.y = acc[u][1] + bi.y;
        o.z = acc[u][2] + bi.z; o.w = acc[u][3] + bi.w;
        *(float4*)&C[(size_t)(m0 + (ty << 2) + u) * ldc + n0 + (tx << 2)] = o;
    }
}

// ---------------- kernels ----------------

__global__ void k_init(const float* __restrict__ e_last,
                       const float* __restrict__ W_ih)
{
    int i = blockIdx.x * blockDim.x + threadIdx.x;
    if (i < Bn * Dn) g_h[i] = e_last[i];
    if (i < Bn * 16) {                     // zero x + pad region of gin
        int b = i >> 4, k = i & 15;
        g_gin[b * GKP + Dn + k] = 0.f;
    }
    for (int j = i; j < N3 * GKP; j += gridDim.x * blockDim.x) {
        int n = j / GKP, k = j - n * GKP;
        g_Wpad[j] = (k < GK) ? W_ih[n * GK + k] : 0.f;
    }
}

// Uk = e_all @ Ua_w + Ua_b    (M = B*S = 8192, N = K = 512)
__global__ void k_uk(const float* __restrict__ e_all,
                     const float* __restrict__ Ua_w,
                     const float* __restrict__ Ua_b)
{
    __shared__ SmemGemm s;
    gemm64<false>(e_all, Dn, Ua_w, Dn, g_Uk, Dn, Ua_b,
                  blockIdx.y * 64, blockIdx.x * 64, 0, 32, s);
}

// per step: q partials, gh partials, and out_{t-1} = h_t @ Wo (+x update)
__global__ void k_qgh(const float* __restrict__ Wa_w,
                      const float* __restrict__ W_hh,
                      const float* __restrict__ Wo_w,
                      const float* __restrict__ Wo_b,
                      float* __restrict__ d_outputs, int t)
{
    __shared__ SmemGemm s;
    const int bx = blockIdx.x;
    if (bx < 32) {                               // q: 8 n-tiles x 4 K-parts
        int part = bx >> 3, nt = bx & 7;
        gemm64<false>(g_h, Dn, Wa_w, Dn, g_qpart[part], Dn, nullptr,
                      0, nt * 64, part * 128, 8, s);
    } else if (bx < 128) {                       // gh: 24 n-tiles x 4 K-parts
        int i = bx - 32;
        int part = i / 24, nt = i - part * 24;
        gemm64<true>(g_h, Dn, W_hh, Dn, g_ghpart[part], N3, nullptr,
                     0, nt * 64, part * 128, 8, s);
    } else {                                     // out_{t-1} block
        if (t == 0) return;
        int tid = threadIdx.x;
        if (tid < 192) {
            int b = tid / 3, c = tid - b * 3;
            const float* hr = &g_h[b * Dn];
            float acc = Wo_b[c];
            #pragma unroll 4
            for (int k = 0; k < Dn; ++k) acc += hr[k] * Wo_w[k * 3 + c];
            d_outputs[((size_t)b * Tn + (t - 1)) * 3 + c] = acc;
            g_gin[b * GKP + Dn + c] = acc;       // x input for this step
        }
    }
}

// per step: attention for batch b = blockIdx.x
__global__ void k_attn(const float* __restrict__ e_all,
                       const float* __restrict__ Wa_b,
                       const float* __restrict__ Va_w,
                       const float* __restrict__ Va_b,
                       float* __restrict__ cross, int t)
{
    __shared__ float qs[Dn];
    __shared__ float vas[Dn];
    __shared__ float ws[Sn];
    __shared__ float red[8];
    __shared__ float smax, sinv;

    const int tid = threadIdx.x;
    const int b = blockIdx.x;

    for (int d = tid; d < Dn; d += 256) {
        float q = Wa_b[d];
        #pragma unroll
        for (int p = 0; p < 4; ++p) q += g_qpart[p][b * Dn + d];
        qs[d] = q;
        vas[d] = Va_w[d];
    }
    __syncthreads();

    const int lane = tid & 31, wid = tid >> 5;
    const float vb0 = Va_b[0];
    const float* ukb = &g_Uk[(size_t)b * Sn * Dn];
    for (int s = wid * 16; s < wid * 16 + 16; ++s) {
        const float* uk = ukb + (size_t)s * Dn;
        float sum = 0.f;
        #pragma unroll
        for (int i = 0; i < 16; ++i) {
            int d = lane + (i << 5);
            sum += tanh_fast(qs[d] + uk[d]) * vas[d];
        }
        #pragma unroll
        for (int o = 16; o > 0; o >>= 1) sum += __shfl_down_sync(0xffffffffu, sum, o);
        if (lane == 0) ws[s] = sum + vb0;
    }
    __syncthreads();

    // softmax over S=128
    float v = (tid < Sn) ? ws[tid] : -3.4e38f;
    #pragma unroll
    for (int o = 16; o > 0; o >>= 1) v = fmaxf(v, __shfl_xor_sync(0xffffffffu, v, o));
    if (lane == 0) red[wid] = v;
    __syncthreads();
    if (tid == 0) {
        float m = red[0];
        #pragma unroll
        for (int i = 1; i < 8; ++i) m = fmaxf(m, red[i]);
        smax = m;
    }
    __syncthreads();
    float e = (tid < Sn) ? __expf(ws[tid] - smax) : 0.f;
    float es = e;
    #pragma unroll
    for (int o = 16; o > 0; o >>= 1) es += __shfl_xor_sync(0xffffffffu, es, o);
    if (lane == 0) red[wid] = es;
    __syncthreads();
    if (tid == 0) {
        float s2 = 0.f;
        #pragma unroll
        for (int i = 0; i < 8; ++i) s2 += red[i];
        sinv = 1.f / s2;
    }
    __syncthreads();
    if (tid < Sn) {
        float w = e * sinv;
        ws[tid] = w;
        cross[((size_t)b * Tn + t) * Sn + tid] = w;
    }
    __syncthreads();

    // ctx = w @ e_all[b]   (each thread owns d and d+256)
    const float* eb = &e_all[(size_t)b * Sn * Dn];
    float a0 = 0.f, a1 = 0.f;
    #pragma unroll 4
    for (int s = 0; s < Sn; ++s) {
        float w = ws[s];
        a0 += w * eb[(size_t)s * Dn + tid];
        a1 += w * eb[(size_t)s * Dn + tid + 256];
    }
    g_gin[b * GKP + tid] = a0;
    g_gin[b * GKP + tid + 256] = a1;
}

// per step: gi partials = gin @ Wpad^T   (N=1536, K=528, split-K 4)
__global__ void k_gi()
{
    __shared__ SmemGemm s;
    const int part = blockIdx.x & 3;
    const int nt = blockIdx.x >> 2;
    const int k0 = (part < 3) ? part * 128 : 384;
    const int ki = (part < 3) ? 8 : 9;
    gemm64<true>(g_gin, GKP, g_Wpad, GKP, g_gipart[part], N3, nullptr,
                 0, nt * 64, k0, ki, s);
}

// per step: GRU gates, h update
__global__ void k_gates(const float* __restrict__ b_ih,
                        const float* __restrict__ b_hh)
{
    int i = blockIdx.x * 256 + threadIdx.x;      // 0..32767
    int b = i >> 9, j = i & 511;
    int base = b * N3 + j;

    float gir = b_ih[j], giz = b_ih[Dn + j], gin_ = b_ih[2 * Dn + j];
    float ghr = b_hh[j], ghz = b_hh[Dn + j], ghn = b_hh[2 * Dn + j];
    #pragma unroll
    for (int p = 0; p < 4; ++p) {
        gir  += g_gipart[p][base];
        giz  += g_gipart[p][base + Dn];
        gin_ += g_gipart[p][base + 2 * Dn];
        ghr  += g_ghpart[p][base];
        ghz  += g_ghpart[p][base + Dn];
        ghn  += g_ghpart[p][base + 2 * Dn];
    }
    float r = 1.f / (1.f + __expf(-(gir + ghr)));
    float z = 1.f / (1.f + __expf(-(giz + ghz)));
    float n = tanhf(gin_ + r * ghn);
    float h = g_h[i];
    g_h[i] = (1.f - z) * n + z * h;
}

// final: out_{T-1} = h_T @ Wo + b,  hT = h_T
__global__ void k_final(const float* __restrict__ Wo_w,
                        const float* __restrict__ Wo_b,
                        float* __restrict__ d_outputs,
                        float* __restrict__ hT)
{
    int i = blockIdx.x * 512 + threadIdx.x;
    hT[i] = g_h[i];
    if (blockIdx.x == 0 && threadIdx.x < 192) {
        int b = threadIdx.x / 3, c = threadIdx.x - b * 3;
        const float* hr = &g_h[b * Dn];
        float acc = Wo_b[c];
        #pragma unroll 4
        for (int k = 0; k < Dn; ++k) acc += hr[k] * Wo_w[k * 3 + c];
        d_outputs[((size_t)b * Tn + (Tn - 1)) * 3 + c] = acc;
    }
}

// ---------------- launch ----------------
extern "C" void kernel_launch(void* const* d_in, const int* in_sizes, int n_in,
                              void* d_out, int out_size)
{
    const float* e_all  = (const float*)d_in[0];
    const float* e_last = (const float*)d_in[1];
    const float* Wa_w   = (const float*)d_in[2];
    const float* Wa_b   = (const float*)d_in[3];
    const float* Ua_w   = (const float*)d_in[4];
    const float* Ua_b   = (const float*)d_in[5];
    const float* Va_w   = (const float*)d_in[6];
    const float* Va_b   = (const float*)d_in[7];
    const float* W_ih   = (const float*)d_in[8];
    const float* W_hh   = (const float*)d_in[9];
    const float* b_ih   = (const float*)d_in[10];
    const float* b_hh   = (const float*)d_in[11];
    const float* Wo_w   = (const float*)d_in[12];
    const float* Wo_b   = (const float*)d_in[13];

    float* out       = (float*)d_out;
    float* d_outputs = out;                        // [B,T,3]  = 12288
    float* hT        = out + Bn * Tn * 3;          // [1,B,D]  = 32768
    float* cross     = hT + Bn * Dn;               // [B,T,S]  = 524288

    k_init<<<512, 256>>>(e_last, W_ih);
    k_uk<<<dim3(Dn / 64, (Bn * Sn) / 64), 256>>>(e_all, Ua_w, Ua_b);

    for (int t = 0; t < Tn; ++t) {
        k_qgh<<<129, 256>>>(Wa_w, W_hh, Wo_w, Wo_b, d_outputs, t);
        k_attn<<<Bn, 256>>>(e_all, Wa_b, Va_w, Va_b, cross, t);
        k_gi<<<96, 256>>>();
        k_gates<<<128, 256>>>(b_ih, b_hh);
    }
    k_final<<<64, 512>>>(Wo_w, Wo_b, d_outputs, hT);
}

// round 3
// speedup vs baseline: 1.1450x; 1.1450x over previous
#include <cuda_runtime.h>
#include <cstdint>

#define Bn 64
#define Sn 128
#define Dn 512
#define Tn 64
#define N3 1536      // 3*D
#define NR 2048      // D + 3*D (combined q|gh GEMM width)
#define GK 515       // D + 3
#define GKP 528      // padded to multiple of 16

// ---------------- scratch (device globals; no allocation) ----------------
__device__ float g_Uk[Bn * Sn * Dn];              // [B,S,D] keys projection
__device__ float g_h[Bn * Dn];                    // hidden state
__device__ float g_recpart[4][Bn * NR];           // split-K partials of [q | gh]
__device__ float g_gipart[4][Bn * N3];            // split-K partials of gi
__device__ float g_gin[Bn * GKP];                 // [ctx | x | zero-pad]
__device__ float g_Wpad[N3 * GKP];                // W_ih zero-padded to K=528
__device__ float g_Wcat[NR * Dn];                 // [Wa_w^T ; W_hh], NT layout [N,K]
__device__ float g_scores[Bn * Sn];               // attention scores

__device__ __forceinline__ float tanh_fast(float x) {
    float y; asm("tanh.approx.f32 %0, %1;" : "=f"(y) : "f"(x)); return y;
}

struct SmemGemm { float As[16][68]; float Bs[16][68]; };

// C[64 x 64] tile of  C = A(MxK) * B  (+bias), BK=16, 256 threads, 4x4 microtile.
// NT=false: B row-major [K,N];  NT=true: B row-major [N,K].
template <bool NT>
__device__ __forceinline__ void gemm64(const float* __restrict__ A, int lda,
                                       const float* __restrict__ B, int ldb,
                                       float* __restrict__ C, int ldc,
                                       const float* __restrict__ bias,
                                       int m0, int n0, int k0, int kiters,
                                       SmemGemm& s)
{
    const int tid = threadIdx.x;
    const int tx = tid & 15, ty = tid >> 4;
    const int am = tid >> 2, ak = (tid & 3) << 2;
    float acc[4][4] = {};

    for (int it = 0; it < kiters; ++it) {
        const int k = k0 + it * 16;
        float4 a4 = *(const float4*)&A[(size_t)(m0 + am) * lda + k + ak];
        float4 b4;
        if (NT) {
            b4 = *(const float4*)&B[(size_t)(n0 + am) * ldb + k + ak];
        } else {
            const int bk = tid >> 4, bn = (tid & 15) << 2;
            b4 = *(const float4*)&B[(size_t)(k + bk) * ldb + n0 + bn];
        }
        __syncthreads();
        s.As[ak + 0][am] = a4.x; s.As[ak + 1][am] = a4.y;
        s.As[ak + 2][am] = a4.z; s.As[ak + 3][am] = a4.w;
        if (NT) {
            s.Bs[ak + 0][am] = b4.x; s.Bs[ak + 1][am] = b4.y;
            s.Bs[ak + 2][am] = b4.z; s.Bs[ak + 3][am] = b4.w;
        } else {
            const int bk = tid >> 4, bn = (tid & 15) << 2;
            *(float4*)&s.Bs[bk][bn] = b4;
        }
        __syncthreads();
        #pragma unroll
        for (int kk = 0; kk < 16; ++kk) {
            float4 av = *(const float4*)&s.As[kk][ty << 2];
            float4 bv = *(const float4*)&s.Bs[kk][tx << 2];
            float a[4] = {av.x, av.y, av.z, av.w};
            float b[4] = {bv.x, bv.y, bv.z, bv.w};
            #pragma unroll
            for (int u = 0; u < 4; ++u)
                #pragma unroll
                for (int v = 0; v < 4; ++v)
                    acc[u][v] += a[u] * b[v];
        }
    }

    float4 bi = make_float4(0.f, 0.f, 0.f, 0.f);
    if (bias) bi = *(const float4*)&bias[n0 + (tx << 2)];
    #pragma unroll
    for (int u = 0; u < 4; ++u) {
        float4 o;
        o.x = acc[u][0] + bi.x; o.y = acc[u][1] + bi.y;
        o.z = acc[u][2] + bi.z; o.w = acc[u][3] + bi.w;
        *(float4*)&C[(size_t)(m0 + (ty << 2) + u) * ldc + n0 + (tx << 2)] = o;
    }
}

// ---------------- kernels ----------------

__global__ void k_init(const float* __restrict__ e_last,
                       const float* __restrict__ W_ih,
                       const float* __restrict__ Wa_w,
                       const float* __restrict__ W_hh)
{
    const int i = blockIdx.x * blockDim.x + threadIdx.x;
    const int stride = gridDim.x * blockDim.x;
    if (i < Bn * Dn) g_h[i] = e_last[i];
    if (i < Bn * 16) {                     // zero x + pad region of gin
        int b = i >> 4, k = i & 15;
        g_gin[b * GKP + Dn + k] = 0.f;
    }
    for (int j = i; j < N3 * GKP; j += stride) {
        int n = j / GKP, k = j - n * GKP;
        g_Wpad[j] = (k < GK) ? W_ih[n * GK + k] : 0.f;
    }
    for (int j = i; j < NR * Dn; j += stride) {
        int n = j >> 9, k = j & 511;
        g_Wcat[j] = (n < Dn) ? Wa_w[k * Dn + n] : W_hh[(size_t)(n - Dn) * Dn + k];
    }
}

// Uk = e_all @ Ua_w + Ua_b    (M = B*S = 8192, N = K = 512)
__global__ void k_uk(const float* __restrict__ e_all,
                     const float* __restrict__ Ua_w,
                     const float* __restrict__ Ua_b)
{
    __shared__ SmemGemm s;
    gemm64<false>(e_all, Dn, Ua_w, Dn, g_Uk, Dn, Ua_b,
                  blockIdx.y * 64, blockIdx.x * 64, 0, 32, s);
}

// per step: [q | gh] partials = h @ Wcat^T, plus out_{t-1} = h_t @ Wo block.
__global__ void k_rec(const float* __restrict__ Wo_w,
                      const float* __restrict__ Wo_b,
                      float* __restrict__ d_outputs, int t)
{
    const int bx = blockIdx.x;
    if (bx < 128) {
        __shared__ SmemGemm s;
        const int part = bx & 3, nt = bx >> 2;        // 32 n-tiles x 4 K-parts
        gemm64<true>(g_h, Dn, g_Wcat, Dn, g_recpart[part], NR, nullptr,
                     0, nt * 64, part * 128, 8, s);
    } else {
        if (t == 0) return;
        const int tid = threadIdx.x;
        if (tid < 192) {
            int b = tid / 3, c = tid - b * 3;
            const float* hr = &g_h[b * Dn];
            float acc = Wo_b[c];
            #pragma unroll 4
            for (int k = 0; k < Dn; ++k) acc += hr[k] * Wo_w[k * 3 + c];
            d_outputs[((size_t)b * Tn + (t - 1)) * 3 + c] = acc;
            g_gin[b * GKP + Dn + c] = acc;            // x input for this step
        }
    }
}

// per step: scores[b, s], 16 s-rows per CTA (2 per warp).  grid = B*8.
__global__ void k_score(const float* __restrict__ Wa_b,
                        const float* __restrict__ Va_w,
                        const float* __restrict__ Va_b)
{
    __shared__ float qs[Dn];
    __shared__ float vas[Dn];
    const int tid = threadIdx.x;
    const int b = blockIdx.x >> 3, ch = blockIdx.x & 7;
    const int lane = tid & 31, wid = tid >> 5;

    for (int d = tid; d < Dn; d += 256) {
        float q = Wa_b[d];
        #pragma unroll
        for (int p = 0; p < 4; ++p) q += g_recpart[p][b * NR + d];
        qs[d] = q;
        vas[d] = Va_w[d];
    }
    __syncthreads();

    const float vb0 = Va_b[0];
    #pragma unroll
    for (int ss = 0; ss < 2; ++ss) {
        const int s = ch * 16 + wid * 2 + ss;
        const float4* uk4 = (const float4*)(g_Uk + ((size_t)b * Sn + s) * Dn);
        float sum = 0.f;
        #pragma unroll
        for (int i = 0; i < 4; ++i) {
            const int v = lane + (i << 5);
            float4 u = uk4[v];
            float4 q4 = *(const float4*)&qs[v << 2];
            float4 a4 = *(const float4*)&vas[v << 2];
            sum += tanh_fast(q4.x + u.x) * a4.x;
            sum += tanh_fast(q4.y + u.y) * a4.y;
            sum += tanh_fast(q4.z + u.z) * a4.z;
            sum += tanh_fast(q4.w + u.w) * a4.w;
        }
        #pragma unroll
        for (int o = 16; o > 0; o >>= 1) sum += __shfl_down_sync(0xffffffffu, sum, o);
        if (lane == 0) g_scores[b * Sn + s] = sum + vb0;
    }
}

// per step: softmax (redundant per CTA) + ctx slice.  grid = B*2, 256 threads.
__global__ void k_ctx(const float* __restrict__ e_all,
                      float* __restrict__ cross, int t)
{
    __shared__ float ws[Sn];
    __shared__ float red[8];
    __shared__ float smax, sinv;
    const int tid = threadIdx.x;
    const int b = blockIdx.x >> 1, dc = blockIdx.x & 1;
    const int lane = tid & 31, wid = tid >> 5;

    float sc = (tid < Sn) ? g_scores[b * Sn + tid] : -3.4e38f;
    float v = sc;
    #pragma unroll
    for (int o = 16; o > 0; o >>= 1) v = fmaxf(v, __shfl_xor_sync(0xffffffffu, v, o));
    if (lane == 0) red[wid] = v;
    __syncthreads();
    if (tid == 0) {
        float m = red[0];
        #pragma unroll
        for (int i = 1; i < 8; ++i) m = fmaxf(m, red[i]);
        smax = m;
    }
    __syncthreads();
    float e = (tid < Sn) ? __expf(sc - smax) : 0.f;
    float es = e;
    #pragma unroll
    for (int o = 16; o > 0; o >>= 1) es += __shfl_xor_sync(0xffffffffu, es, o);
    if (lane == 0) red[wid] = es;
    __syncthreads();
    if (tid == 0) {
        float s2 = 0.f;
        #pragma unroll
        for (int i = 0; i < 8; ++i) s2 += red[i];
        sinv = 1.f / s2;
    }
    __syncthreads();
    if (tid < Sn) {
        float w = e * sinv;
        ws[tid] = w;
        if (dc == 0) cross[((size_t)b * Tn + t) * Sn + tid] = w;
    }
    __syncthreads();

    // ctx columns d = dc*256 + tid
    const int d = dc * 256 + tid;
    const float* eb = e_all + (size_t)b * Sn * Dn + d;
    float a = 0.f;
    #pragma unroll 8
    for (int s = 0; s < Sn; ++s)
        a += ws[s] * eb[(size_t)s * Dn];
    g_gin[b * GKP + d] = a;
}

// per step: gi partials = gin @ Wpad^T   (N=1536, K=528, split-K 4)
__global__ void k_gi()
{
    __shared__ SmemGemm s;
    const int part = blockIdx.x & 3;
    const int nt = blockIdx.x >> 2;
    const int k0 = (part < 3) ? part * 128 : 384;
    const int ki = (part < 3) ? 8 : 9;
    gemm64<true>(g_gin, GKP, g_Wpad, GKP, g_gipart[part], N3, nullptr,
                 0, nt * 64, k0, ki, s);
}

// per step: GRU gates, h update
__global__ void k_gates(const float* __restrict__ b_ih,
                        const float* __restrict__ b_hh)
{
    int i = blockIdx.x * 256 + threadIdx.x;      // 0..32767
    int b = i >> 9, j = i & 511;
    int gbase = b * N3 + j;
    int rbase = b * NR + Dn + j;

    float gir = b_ih[j], giz = b_ih[Dn + j], gin_ = b_ih[2 * Dn + j];
    float ghr = b_hh[j], ghz = b_hh[Dn + j], ghn = b_hh[2 * Dn + j];
    #pragma unroll
    for (int p = 0; p < 4; ++p) {
        gir  += g_gipart[p][gbase];
        giz  += g_gipart[p][gbase + Dn];
        gin_ += g_gipart[p][gbase + 2 * Dn];
        ghr  += g_recpart[p][rbase];
        ghz  += g_recpart[p][rbase + Dn];
        ghn  += g_recpart[p][rbase + 2 * Dn];
    }
    float r = 1.f / (1.f + __expf(-(gir + ghr)));
    float z = 1.f / (1.f + __expf(-(giz + ghz)));
    float n = tanhf(gin_ + r * ghn);
    float h = g_h[i];
    g_h[i] = (1.f - z) * n + z * h;
}

// final: out_{T-1} = h_T @ Wo + b,  hT = h_T
__global__ void k_final(const float* __restrict__ Wo_w,
                        const float* __restrict__ Wo_b,
                        float* __restrict__ d_outputs,
                        float* __restrict__ hT)
{
    int i = blockIdx.x * 512 + threadIdx.x;
    hT[i] = g_h[i];
    if (blockIdx.x == 0 && threadIdx.x < 192) {
        int b = threadIdx.x / 3, c = threadIdx.x - b * 3;
        const float* hr = &g_h[b * Dn];
        float acc = Wo_b[c];
        #pragma unroll 4
        for (int k = 0; k < Dn; ++k) acc += hr[k] * Wo_w[k * 3 + c];
        d_outputs[((size_t)b * Tn + (Tn - 1)) * 3 + c] = acc;
    }
}

// ---------------- launch ----------------
extern "C" void kernel_launch(void* const* d_in, const int* in_sizes, int n_in,
                              void* d_out, int out_size)
{
    const float* e_all  = (const float*)d_in[0];
    const float* e_last = (const float*)d_in[1];
    const float* Wa_w   = (const float*)d_in[2];
    const float* Wa_b   = (const float*)d_in[3];
    const float* Ua_w   = (const float*)d_in[4];
    const float* Ua_b   = (const float*)d_in[5];
    const float* Va_w   = (const float*)d_in[6];
    const float* Va_b   = (const float*)d_in[7];
    const float* W_ih   = (const float*)d_in[8];
    const float* W_hh   = (const float*)d_in[9];
    const float* b_ih   = (const float*)d_in[10];
    const float* b_hh   = (const float*)d_in[11];
    const float* Wo_w   = (const float*)d_in[12];
    const float* Wo_b   = (const float*)d_in[13];

    float* out       = (float*)d_out;
    float* d_outputs = out;                        // [B,T,3]
    float* hT        = out + Bn * Tn * 3;          // [1,B,D]
    float* cross     = hT + Bn * Dn;               // [B,T,S]

    k_init<<<592, 256>>>(e_last, W_ih, Wa_w, W_hh);
    k_uk<<<dim3(Dn / 64, (Bn * Sn) / 64), 256>>>(e_all, Ua_w, Ua_b);

    for (int t = 0; t < Tn; ++t) {
        k_rec<<<129, 256>>>(Wo_w, Wo_b, d_outputs, t);
        k_score<<<Bn * 8, 256>>>(Wa_b, Va_w, Va_b);
        k_ctx<<<Bn * 2, 256>>>(e_all, cross, t);
        k_gi<<<96, 256>>>();
        k_gates<<<128, 256>>>(b_ih, b_hh);
    }
    k_final<<<64, 512>>>(Wo_w, Wo_b, d_outputs, hT);
}